// round 15
// baseline (speedup 1.0000x reference)
#include <cuda_runtime.h>
#include <cuda_fp16.h>
#include <cstdint>
#include <cstddef>

#define THREADS 128
#define GRID    740          // 148 SMs x 5 CTAs
#define NTILES  8192         // 524288 rows / 64

#define S 144                // row stride (bytes), conflict-free
// smem byte offsets (per CTA, tile M=64)
#define AP0   0              // A0: 64 x 64 fp16 (h1 pos j)
#define AP1   9216           // A1: 64 x 64 fp16 (h1 pos 1+j)
#define B1    18432          // W2 reshaped 32 x 64 (fp16)
#define B2HI  23040          // Wp column-permuted 64 x 64 (fp16 hi/lo)
#define B2LO  32256
#define CST   41472          // floats: W1[128], b1[32], b2e[64], bp[64]
#define SMEM_BYTES (41472 + 288 * 4)

static __device__ __forceinline__ uint32_t smem_u32(const void* p) {
    uint32_t a;
    asm("{ .reg .u64 t; cvta.to.shared.u64 t, %1; cvt.u32.u64 %0, t; }" : "=r"(a) : "l"(p));
    return a;
}
static __device__ __forceinline__ uint16_t h16(float v) {
    __half h = __float2half_rn(v);
    return reinterpret_cast<uint16_t&>(h);
}
static __device__ __forceinline__ uint32_t h2pack(float vlo, float vhi) {
    uint32_t r;
    asm("cvt.rn.f16x2.f32 %0, %1, %2;" : "=r"(r) : "f"(vhi), "f"(vlo));
    return r;
}
static __device__ __forceinline__ void hsplit(float v, uint16_t& h, uint16_t& l) {
    __half hh = __float2half_rn(v);
    float vh = __half2float(hh);
    __half hl = __float2half_rn(v - vh);
    h = reinterpret_cast<uint16_t&>(hh);
    l = reinterpret_cast<uint16_t&>(hl);
}

#define LDSM4(r, addr) \
    asm volatile("ldmatrix.sync.aligned.m8n8.x4.shared.b16 {%0,%1,%2,%3}, [%4];" \
        : "=r"((r)[0]), "=r"((r)[1]), "=r"((r)[2]), "=r"((r)[3]) : "r"(addr))

#define MMA(d, a, b0, b1) \
    asm volatile("mma.sync.aligned.m16n8k16.row.col.f32.f16.f16.f32 " \
        "{%0,%1,%2,%3}, {%4,%5,%6,%7}, {%8,%9}, {%0,%1,%2,%3};" \
        : "+f"((d)[0]), "+f"((d)[1]), "+f"((d)[2]), "+f"((d)[3]) \
        : "r"((a)[0]), "r"((a)[1]), "r"((a)[2]), "r"((a)[3]), "r"(b0), "r"(b1))

__global__ __launch_bounds__(THREADS, 5)
void cnn_encoder_mma11(const float* __restrict__ x,
                       const float* __restrict__ W1, const float* __restrict__ b1,
                       const float* __restrict__ W2, const float* __restrict__ b2,
                       const float* __restrict__ Wp, const float* __restrict__ bp,
                       float* __restrict__ out)
{
    extern __shared__ char smc[];
    const uint32_t sb = smem_u32(smc);
    float* cst = (float*)(smc + CST);   // W1[0:128) b1[128:160) b2e[160:224) bp[224:288)

    const int t    = threadIdx.x;
    const int wp   = t >> 5;      // 0..3, owns rows 16*wp .. +16
    const int lane = t & 31;
    const int g    = lane >> 2;
    const int tg   = lane & 3;

    // ---- stage consts + B tiles (once) ----
    if (t < 128) cst[t] = W1[t];
    if (t < 32)  cst[128 + t] = b1[t];
    if (t < 64)  { cst[160 + t] = b2[t & 31]; cst[224 + t] = bp[t]; }

    // B1 = W2 reshaped [c2=32][k=64], single fp16
    for (int i = t; i < 32 * 64; i += THREADS) {
        int c2 = i >> 6, kk = i & 63;
        *(uint16_t*)(smc + B1 + c2 * S + kk * 2) = h16(W2[i]);
    }
    // B2[o][kk] = Wp[o][2*(kk&31) + (kk>>5)]  (k = GEMM1-output column), fp16 hi/lo
    for (int i = t; i < 64 * 64; i += THREADS) {
        int o = i >> 6, kk = i & 63;
        uint16_t h, l; hsplit(Wp[o * 64 + 2 * (kk & 31) + (kk >> 5)], h, l);
        *(uint16_t*)(smc + B2HI + o * S + kk * 2) = h;
        *(uint16_t*)(smc + B2LO + o * S + kk * 2) = l;
    }

    // ldmatrix lane addressing (validated pattern)
    const int mat  = lane >> 3;
    const int lrow = (lane & 7) + 8 * (mat & 1);
    const int kby  = 16 * (mat >> 1);
    const uint32_t a0b = sb + AP0 + (16 * wp + lrow) * S + kby;
    const uint32_t a1b = sb + AP1 + (16 * wp + lrow) * S + kby;
    const uint32_t b1b = sb + B1 + lrow * S + kby;      // rows 0-15; +16*S for 16-31
    const uint32_t b2b = sb + B2HI + lrow * S + kby;    // +grp*16*S for row groups

    const int row = t & 63;       // conv: row within 64-row tile
    const int qh  = t >> 6;       // conv: 16-channel half 0..1

    // per-thread convert biases (b2e) and output biases (bp) read from cst on the fly
    __syncthreads();

    for (int tile = blockIdx.x; tile < NTILES; tile += GRID) {
        // ================= conv1 -> AP0/AP1 (single fp16, packed cvt) =================
        {
            const float4* xr = (const float4*)(x + ((size_t)tile * 64 + row) * 8);
            float4 xa = xr[0], xb = xr[1];
            const float x0 = xa.x, x1 = xa.y, x2 = xa.z, x3 = xa.w;
            const float x4 = xb.x, x5 = xb.y, x6 = xb.z, x7 = xb.w;

            uint32_t a0[16], a1[16];
            #pragma unroll
            for (int u = 0; u < 16; u++) {
                int c1 = 16 * qh + u;
                float4 wv = ((const float4*)cst)[c1];
                float bb  = cst[128 + c1];
                float p0 = fmaxf(bb + wv.x * x0 + wv.y * x1 + wv.z * x4 + wv.w * x5, 0.f);
                float p1 = fmaxf(bb + wv.x * x1 + wv.y * x2 + wv.z * x5 + wv.w * x6, 0.f);
                float p2 = fmaxf(bb + wv.x * x2 + wv.y * x3 + wv.z * x6 + wv.w * x7, 0.f);
                a0[u] = h2pack(p0, p1);
                a1[u] = h2pack(p1, p2);
            }
            char* base = smc + row * S + 64 * qh;
            #pragma unroll
            for (int q = 0; q < 4; q++) {
                *(uint4*)(base + AP0 + 16 * q) = make_uint4(a0[4*q], a0[4*q+1], a0[4*q+2], a0[4*q+3]);
                *(uint4*)(base + AP1 + 16 * q) = make_uint4(a1[4*q], a1[4*q+1], a1[4*q+2], a1[4*q+3]);
            }
        }
        __syncthreads();

        // ========= GEMM1: rows 16wp..+16, BOTH parities, all 32 c2 =========
        float acc1[2][4][4];   // [parity][nf][reg]
        #pragma unroll
        for (int p = 0; p < 2; p++)
            #pragma unroll
            for (int nf = 0; nf < 4; nf++)
                #pragma unroll
                for (int i = 0; i < 4; i++) acc1[p][nf][i] = 0.f;

        #pragma unroll
        for (int kt = 0; kt < 4; kt++) {
            uint32_t bA[4], bB[4], a0f[4], a1f[4];
            LDSM4(bA, b1b + kt * 32);                // c2 rows 0-15 -> nf0,nf1
            LDSM4(bB, b1b + 16 * S + kt * 32);       // c2 rows 16-31 -> nf2,nf3
            LDSM4(a0f, a0b + kt * 32);
            LDSM4(a1f, a1b + kt * 32);
            MMA(acc1[0][0], a0f, bA[0], bA[2]);
            MMA(acc1[0][1], a0f, bA[1], bA[3]);
            MMA(acc1[0][2], a0f, bB[0], bB[2]);
            MMA(acc1[0][3], a0f, bB[1], bB[3]);
            MMA(acc1[1][0], a1f, bA[0], bA[2]);
            MMA(acc1[1][1], a1f, bA[1], bA[3]);
            MMA(acc1[1][2], a1f, bB[0], bB[2]);
            MMA(acc1[1][3], a1f, bB[1], bB[3]);
        }
        __syncthreads();   // all warps done reading AP0/AP1 (+B1); frees AP for next conv

        // ---- in-register convert: D1 frags -> GEMM2 A frags (bias+relu+pack) ----
        uint32_t a2f[4][4];   // [kt][reg] : A fragment for GEMM2 k-chunk kt
        #pragma unroll
        for (int p = 0; p < 2; p++) {
            #pragma unroll
            for (int nf = 0; nf < 4; nf++) {
                int nfg = 4 * p + nf;               // GEMM1-output n-frag 0..7 = GEMM2 k-frag
                float ba = cst[160 + 8 * nfg + 2 * tg];
                float bc = cst[160 + 8 * nfg + 2 * tg + 1];
                float f00 = fmaxf(acc1[p][nf][0] + ba, 0.f);
                float f01 = fmaxf(acc1[p][nf][1] + bc, 0.f);
                float f10 = fmaxf(acc1[p][nf][2] + ba, 0.f);
                float f11 = fmaxf(acc1[p][nf][3] + bc, 0.f);
                int kt = nfg >> 1, hh = nfg & 1;
                a2f[kt][2 * hh]     = h2pack(f00, f01);   // rows g,   k 2tg..
                a2f[kt][2 * hh + 1] = h2pack(f10, f11);   // rows g+8, k 2tg..
            }
        }

        // ========= GEMM2: rows 16wp..+16, all 64 out cols (A in regs) =========
        float acc2[8][4];
        #pragma unroll
        for (int nf = 0; nf < 8; nf++) {
            float p0 = cst[224 + 8 * nf + 2 * tg];
            float p1 = cst[224 + 8 * nf + 2 * tg + 1];
            acc2[nf][0] = p0; acc2[nf][1] = p1; acc2[nf][2] = p0; acc2[nf][3] = p1;
        }

        #pragma unroll
        for (int kt = 0; kt < 4; kt++) {
            #pragma unroll
            for (int grp = 0; grp < 4; grp++) {      // hi part
                uint32_t bh[4];
                LDSM4(bh, b2b + grp * (16 * S) + kt * 32);
                MMA(acc2[2 * grp],     a2f[kt], bh[0], bh[2]);
                MMA(acc2[2 * grp + 1], a2f[kt], bh[1], bh[3]);
            }
            #pragma unroll
            for (int grp = 0; grp < 4; grp++) {      // lo part
                uint32_t bl[4];
                LDSM4(bl, b2b + (B2LO - B2HI) + grp * (16 * S) + kt * 32);
                MMA(acc2[2 * grp],     a2f[kt], bl[0], bl[2]);
                MMA(acc2[2 * grp + 1], a2f[kt], bl[1], bl[3]);
            }
        }

        // ---- epilogue: -> out (bias already in acc init) ----
        {
            size_t r0 = (size_t)tile * 64 + 16 * wp + g;
            #pragma unroll
            for (int nf = 0; nf < 8; nf++) {
                int ncol = 8 * nf + 2 * tg;
                *(float2*)(out + r0 * 64 + ncol)       = make_float2(acc2[nf][0], acc2[nf][1]);
                *(float2*)(out + (r0 + 8) * 64 + ncol) = make_float2(acc2[nf][2], acc2[nf][3]);
            }
        }
        // no trailing barrier: next conv writes AP only after the post-GEMM1 sync
    }
}

extern "C" void kernel_launch(void* const* d_in, const int* in_sizes, int n_in,
                              void* d_out, int out_size)
{
    const float* x  = (const float*)d_in[0];
    const float* W1 = (const float*)d_in[1];
    const float* b1 = (const float*)d_in[2];
    const float* W2 = (const float*)d_in[3];
    const float* b2 = (const float*)d_in[4];
    const float* Wp = (const float*)d_in[5];
    const float* bp = (const float*)d_in[6];
    float* out = (float*)d_out;

    cudaFuncSetAttribute(cnn_encoder_mma11,
                         cudaFuncAttributeMaxDynamicSharedMemorySize, SMEM_BYTES);

    cnn_encoder_mma11<<<GRID, THREADS, SMEM_BYTES>>>(x, W1, b1, W2, b2, Wp, bp, out);
}

// round 16
// speedup vs baseline: 1.1841x; 1.1841x over previous
#include <cuda_runtime.h>
#include <cuda_fp16.h>
#include <cstdint>
#include <cstddef>

#define THREADS 128
#define GRID    888          // 148 SMs x 6 CTAs
#define NTILES  8192         // 524288 rows / 64

#define S 144                // row stride (bytes), conflict-free
// smem byte offsets (per CTA, tile M=64)
#define AP0   0              // A0: 64 x 64 fp16 (h1 pos j)
#define AP1   9216           // A1: 64 x 64 fp16 (h1 pos 1+j)
#define B1    18432          // W2 reshaped 32 x 64 (fp16)
#define B2    23040          // Wp column-permuted 64 x 64 (single fp16)
#define CST   32256          // floats: W1[128], b1[32], b2e[64], bp[64]
#define SMEM_BYTES (32256 + 288 * 4)

static __device__ __forceinline__ uint32_t smem_u32(const void* p) {
    uint32_t a;
    asm("{ .reg .u64 t; cvta.to.shared.u64 t, %1; cvt.u32.u64 %0, t; }" : "=r"(a) : "l"(p));
    return a;
}
static __device__ __forceinline__ uint16_t h16(float v) {
    __half h = __float2half_rn(v);
    return reinterpret_cast<uint16_t&>(h);
}
static __device__ __forceinline__ uint32_t h2pack(float vlo, float vhi) {
    uint32_t r;
    asm("cvt.rn.f16x2.f32 %0, %1, %2;" : "=r"(r) : "f"(vhi), "f"(vlo));
    return r;
}

#define LDSM4(r, addr) \
    asm volatile("ldmatrix.sync.aligned.m8n8.x4.shared.b16 {%0,%1,%2,%3}, [%4];" \
        : "=r"((r)[0]), "=r"((r)[1]), "=r"((r)[2]), "=r"((r)[3]) : "r"(addr))

#define MMA(d, a, b0, b1) \
    asm volatile("mma.sync.aligned.m16n8k16.row.col.f32.f16.f16.f32 " \
        "{%0,%1,%2,%3}, {%4,%5,%6,%7}, {%8,%9}, {%0,%1,%2,%3};" \
        : "+f"((d)[0]), "+f"((d)[1]), "+f"((d)[2]), "+f"((d)[3]) \
        : "r"((a)[0]), "r"((a)[1]), "r"((a)[2]), "r"((a)[3]), "r"(b0), "r"(b1))

__global__ __launch_bounds__(THREADS, 6)
void cnn_encoder_mma12(const float* __restrict__ x,
                       const float* __restrict__ W1, const float* __restrict__ b1,
                       const float* __restrict__ W2, const float* __restrict__ b2,
                       const float* __restrict__ Wp, const float* __restrict__ bp,
                       float* __restrict__ out)
{
    extern __shared__ char smc[];
    const uint32_t sb = smem_u32(smc);
    float* cst = (float*)(smc + CST);   // W1[0:128) b1[128:160) b2e[160:224) bp[224:288)

    const int t    = threadIdx.x;
    const int wp   = t >> 5;      // 0..3, owns rows 16*wp .. +16
    const int lane = t & 31;
    const int g    = lane >> 2;
    const int tg   = lane & 3;

    // ---- stage consts + B tiles (once) ----
    if (t < 128) cst[t] = W1[t];
    if (t < 32)  cst[128 + t] = b1[t];
    if (t < 64)  { cst[160 + t] = b2[t & 31]; cst[224 + t] = bp[t]; }

    // B1 = W2 reshaped [c2=32][k=64], single fp16
    for (int i = t; i < 32 * 64; i += THREADS) {
        int c2 = i >> 6, kk = i & 63;
        *(uint16_t*)(smc + B1 + c2 * S + kk * 2) = h16(W2[i]);
    }
    // B2[o][kk] = Wp[o][2*(kk&31) + (kk>>5)]  (k = GEMM1-output column), single fp16
    for (int i = t; i < 64 * 64; i += THREADS) {
        int o = i >> 6, kk = i & 63;
        *(uint16_t*)(smc + B2 + o * S + kk * 2) = h16(Wp[o * 64 + 2 * (kk & 31) + (kk >> 5)]);
    }

    // ldmatrix lane addressing (validated pattern)
    const int mat  = lane >> 3;
    const int lrow = (lane & 7) + 8 * (mat & 1);
    const int kby  = 16 * (mat >> 1);
    const uint32_t a0b = sb + AP0 + (16 * wp + lrow) * S + kby;
    const uint32_t a1b = sb + AP1 + (16 * wp + lrow) * S + kby;
    const uint32_t b1b = sb + B1 + lrow * S + kby;      // rows 0-15; +16*S for 16-31
    const uint32_t b2b = sb + B2 + lrow * S + kby;      // +grp*16*S for row groups

    const int row = t & 63;       // conv: row within 64-row tile
    const int qh  = t >> 6;       // conv: 16-channel half 0..1

    __syncthreads();

    for (int tile = blockIdx.x; tile < NTILES; tile += GRID) {
        // ================= conv1 -> AP0/AP1 (single fp16, packed cvt) =================
        {
            const float4* xr = (const float4*)(x + ((size_t)tile * 64 + row) * 8);
            float4 xa = xr[0], xb = xr[1];
            const float x0 = xa.x, x1 = xa.y, x2 = xa.z, x3 = xa.w;
            const float x4 = xb.x, x5 = xb.y, x6 = xb.z, x7 = xb.w;

            uint32_t a0[16], a1[16];
            #pragma unroll
            for (int u = 0; u < 16; u++) {
                int c1 = 16 * qh + u;
                float4 wv = ((const float4*)cst)[c1];
                float bb  = cst[128 + c1];
                float p0 = fmaxf(bb + wv.x * x0 + wv.y * x1 + wv.z * x4 + wv.w * x5, 0.f);
                float p1 = fmaxf(bb + wv.x * x1 + wv.y * x2 + wv.z * x5 + wv.w * x6, 0.f);
                float p2 = fmaxf(bb + wv.x * x2 + wv.y * x3 + wv.z * x6 + wv.w * x7, 0.f);
                a0[u] = h2pack(p0, p1);
                a1[u] = h2pack(p1, p2);
            }
            char* base = smc + row * S + 64 * qh;
            #pragma unroll
            for (int q = 0; q < 4; q++) {
                *(uint4*)(base + AP0 + 16 * q) = make_uint4(a0[4*q], a0[4*q+1], a0[4*q+2], a0[4*q+3]);
                *(uint4*)(base + AP1 + 16 * q) = make_uint4(a1[4*q], a1[4*q+1], a1[4*q+2], a1[4*q+3]);
            }
        }
        __syncthreads();

        // ========= GEMM1: rows 16wp..+16, BOTH parities, all 32 c2 =========
        float acc1[2][4][4];   // [parity][nf][reg]
        #pragma unroll
        for (int p = 0; p < 2; p++)
            #pragma unroll
            for (int nf = 0; nf < 4; nf++)
                #pragma unroll
                for (int i = 0; i < 4; i++) acc1[p][nf][i] = 0.f;

        #pragma unroll
        for (int kt = 0; kt < 4; kt++) {
            uint32_t bA[4], bB[4], a0f[4], a1f[4];
            LDSM4(bA, b1b + kt * 32);                // c2 rows 0-15 -> nf0,nf1
            LDSM4(bB, b1b + 16 * S + kt * 32);       // c2 rows 16-31 -> nf2,nf3
            LDSM4(a0f, a0b + kt * 32);
            LDSM4(a1f, a1b + kt * 32);
            MMA(acc1[0][0], a0f, bA[0], bA[2]);
            MMA(acc1[0][1], a0f, bA[1], bA[3]);
            MMA(acc1[0][2], a0f, bB[0], bB[2]);
            MMA(acc1[0][3], a0f, bB[1], bB[3]);
            MMA(acc1[1][0], a1f, bA[0], bA[2]);
            MMA(acc1[1][1], a1f, bA[1], bA[3]);
            MMA(acc1[1][2], a1f, bB[0], bB[2]);
            MMA(acc1[1][3], a1f, bB[1], bB[3]);
        }
        __syncthreads();   // all warps done reading AP0/AP1; frees AP for next conv

        // ---- in-register convert: D1 frags -> GEMM2 A frags (bias+relu+pack) ----
        uint32_t a2f[4][4];   // [kt][reg] : A fragment for GEMM2 k-chunk kt
        #pragma unroll
        for (int p = 0; p < 2; p++) {
            #pragma unroll
            for (int nf = 0; nf < 4; nf++) {
                int nfg = 4 * p + nf;               // GEMM1-output n-frag = GEMM2 k-frag
                float ba = cst[160 + 8 * nfg + 2 * tg];
                float bc = cst[160 + 8 * nfg + 2 * tg + 1];
                float f00 = fmaxf(acc1[p][nf][0] + ba, 0.f);
                float f01 = fmaxf(acc1[p][nf][1] + bc, 0.f);
                float f10 = fmaxf(acc1[p][nf][2] + ba, 0.f);
                float f11 = fmaxf(acc1[p][nf][3] + bc, 0.f);
                int kt = nfg >> 1, hh = nfg & 1;
                a2f[kt][2 * hh]     = h2pack(f00, f01);   // rows g,   k 2tg..
                a2f[kt][2 * hh + 1] = h2pack(f10, f11);   // rows g+8, k 2tg..
            }
        }

        // ========= GEMM2: rows 16wp..+16, all 64 out cols (A in regs, B single) =========
        float acc2[8][4];
        #pragma unroll
        for (int nf = 0; nf < 8; nf++) {
            float p0 = cst[224 + 8 * nf + 2 * tg];
            float p1 = cst[224 + 8 * nf + 2 * tg + 1];
            acc2[nf][0] = p0; acc2[nf][1] = p1; acc2[nf][2] = p0; acc2[nf][3] = p1;
        }

        #pragma unroll
        for (int kt = 0; kt < 4; kt++) {
            #pragma unroll
            for (int grp = 0; grp < 4; grp++) {
                uint32_t bh[4];
                LDSM4(bh, b2b + grp * (16 * S) + kt * 32);
                MMA(acc2[2 * grp],     a2f[kt], bh[0], bh[2]);
                MMA(acc2[2 * grp + 1], a2f[kt], bh[1], bh[3]);
            }
        }

        // ---- epilogue: -> out (bias already in acc init) ----
        {
            size_t r0 = (size_t)tile * 64 + 16 * wp + g;
            #pragma unroll
            for (int nf = 0; nf < 8; nf++) {
                int ncol = 8 * nf + 2 * tg;
                *(float2*)(out + r0 * 64 + ncol)       = make_float2(acc2[nf][0], acc2[nf][1]);
                *(float2*)(out + (r0 + 8) * 64 + ncol) = make_float2(acc2[nf][2], acc2[nf][3]);
            }
        }
        // no trailing barrier: next conv writes AP only after the post-GEMM1 sync
    }
}

extern "C" void kernel_launch(void* const* d_in, const int* in_sizes, int n_in,
                              void* d_out, int out_size)
{
    const float* x  = (const float*)d_in[0];
    const float* W1 = (const float*)d_in[1];
    const float* b1 = (const float*)d_in[2];
    const float* W2 = (const float*)d_in[3];
    const float* b2 = (const float*)d_in[4];
    const float* Wp = (const float*)d_in[5];
    const float* bp = (const float*)d_in[6];
    float* out = (float*)d_out;

    cudaFuncSetAttribute(cnn_encoder_mma12,
                         cudaFuncAttributeMaxDynamicSharedMemorySize, SMEM_BYTES);

    cnn_encoder_mma12<<<GRID, THREADS, SMEM_BYTES>>>(x, W1, b1, W2, b2, Wp, bp, out);
}

// round 17
// speedup vs baseline: 1.3063x; 1.1032x over previous
#include <cuda_runtime.h>
#include <cuda_fp16.h>
#include <cstdint>
#include <cstddef>

#define THREADS 128
#define GRID    888          // 148 SMs x 6 CTAs
#define NTILES  8192         // 524288 rows / 64

#define S 144                // row stride (bytes), conflict-free
// smem: only B tiles + consts (NO A tiles — A lives in registers)
#define B1    0              // W2 reshaped 32 x 64 (fp16)
#define B2    4608           // Wp column-permuted 64 x 64 (single fp16)
#define CST   13824          // floats: W1[128], b1[32], b2e[64], bp[64]
#define SMEM_BYTES (13824 + 288 * 4)

static __device__ __forceinline__ uint32_t smem_u32(const void* p) {
    uint32_t a;
    asm("{ .reg .u64 t; cvta.to.shared.u64 t, %1; cvt.u32.u64 %0, t; }" : "=r"(a) : "l"(p));
    return a;
}
static __device__ __forceinline__ uint16_t h16(float v) {
    __half h = __float2half_rn(v);
    return reinterpret_cast<uint16_t&>(h);
}
static __device__ __forceinline__ uint32_t h2pack(float vlo, float vhi) {
    uint32_t r;
    asm("cvt.rn.f16x2.f32 %0, %1, %2;" : "=r"(r) : "f"(vhi), "f"(vlo));
    return r;
}

#define LDSM4(r, addr) \
    asm volatile("ldmatrix.sync.aligned.m8n8.x4.shared.b16 {%0,%1,%2,%3}, [%4];" \
        : "=r"((r)[0]), "=r"((r)[1]), "=r"((r)[2]), "=r"((r)[3]) : "r"(addr))

#define MMA(d, a, b0, b1) \
    asm volatile("mma.sync.aligned.m16n8k16.row.col.f32.f16.f16.f32 " \
        "{%0,%1,%2,%3}, {%4,%5,%6,%7}, {%8,%9}, {%0,%1,%2,%3};" \
        : "+f"((d)[0]), "+f"((d)[1]), "+f"((d)[2]), "+f"((d)[3]) \
        : "r"((a)[0]), "r"((a)[1]), "r"((a)[2]), "r"((a)[3]), "r"(b0), "r"(b1))

__global__ __launch_bounds__(THREADS, 6)
void cnn_encoder_mma13(const float* __restrict__ x,
                       const float* __restrict__ W1, const float* __restrict__ b1,
                       const float* __restrict__ W2, const float* __restrict__ b2,
                       const float* __restrict__ Wp, const float* __restrict__ bp,
                       float* __restrict__ out)
{
    extern __shared__ char smc[];
    const uint32_t sb = smem_u32(smc);
    float* cst = (float*)(smc + CST);   // W1[0:128) b1[128:160) b2e[160:224) bp[224:288)

    const int t    = threadIdx.x;
    const int wp   = t >> 5;      // warp owns rows 16*wp .. +16 of each tile
    const int lane = t & 31;
    const int g    = lane >> 2;
    const int tg   = lane & 3;

    // ---- stage consts + B tiles (once) ----
    if (t < 128) cst[t] = W1[t];
    if (t < 32)  cst[128 + t] = b1[t];
    if (t < 64)  { cst[160 + t] = b2[t & 31]; cst[224 + t] = bp[t]; }

    // B1 = W2 reshaped [c2=32][k=64], single fp16
    for (int i = t; i < 32 * 64; i += THREADS) {
        int c2 = i >> 6, kk = i & 63;
        *(uint16_t*)(smc + B1 + c2 * S + kk * 2) = h16(W2[i]);
    }
    // B2[o][kk] = Wp[o][2*(kk&31) + (kk>>5)]  (k = GEMM1-output column), single fp16
    for (int i = t; i < 64 * 64; i += THREADS) {
        int o = i >> 6, kk = i & 63;
        *(uint16_t*)(smc + B2 + o * S + kk * 2) = h16(Wp[o * 64 + 2 * (kk & 31) + (kk >> 5)]);
    }

    // ldmatrix lane addressing (validated pattern) for B tiles
    const int mat  = lane >> 3;
    const int lrow = (lane & 7) + 8 * (mat & 1);
    const int kby  = 16 * (mat >> 1);
    const uint32_t b1b = sb + B1 + lrow * S + kby;      // c2 rows 0-15; +16*S for 16-31
    const uint32_t b2b = sb + B2 + lrow * S + kby;      // +grp*16*S for row groups

    __syncthreads();   // the ONLY barrier: B tiles ready; warps independent after this

    for (int tile = blockIdx.x; tile < NTILES; tile += GRID) {
        // ===== conv1 directly into A fragments (zero smem, zero shuffles) =====
        // lane (4g+tg) computes rows {g, g+8} (of this warp's 16), channels {tg+4u}.
        uint32_t af0[4][4], af1[4][4];   // [kt][reg] A frags for parity buf 0 / 1
        {
            const size_t rbase = (size_t)tile * 64 + 16 * wp + g;
            const float4* xr0 = (const float4*)(x + rbase * 8);
            const float4* xr1 = (const float4*)(x + (rbase + 8) * 8);
            float4 xa0 = xr0[0], xb0 = xr0[1];
            float4 xa1 = xr1[0], xb1 = xr1[1];

            #pragma unroll
            for (int u = 0; u < 8; u++) {
                int c = tg + 4 * u;
                float4 wv = ((const float4*)cst)[c];
                float bb  = cst[128 + c];
                // row g
                float p0 = fmaxf(bb + wv.x * xa0.x + wv.y * xa0.y + wv.z * xb0.x + wv.w * xb0.y, 0.f);
                float p1 = fmaxf(bb + wv.x * xa0.y + wv.y * xa0.z + wv.z * xb0.y + wv.w * xb0.z, 0.f);
                float p2 = fmaxf(bb + wv.x * xa0.z + wv.y * xa0.w + wv.z * xb0.z + wv.w * xb0.w, 0.f);
                // row g+8
                float q0 = fmaxf(bb + wv.x * xa1.x + wv.y * xa1.y + wv.z * xb1.x + wv.w * xb1.y, 0.f);
                float q1 = fmaxf(bb + wv.x * xa1.y + wv.y * xa1.z + wv.z * xb1.y + wv.w * xb1.z, 0.f);
                float q2 = fmaxf(bb + wv.x * xa1.z + wv.y * xa1.w + wv.z * xb1.z + wv.w * xb1.w, 0.f);
                int kt = u >> 1, hh = u & 1;
                af0[kt][2 * hh + 0] = h2pack(p0, p1);   // (row g,   A0 col pair of channel c)
                af0[kt][2 * hh + 1] = h2pack(q0, q1);   // (row g+8)
                af1[kt][2 * hh + 0] = h2pack(p1, p2);   // A1 = positions (1+j)
                af1[kt][2 * hh + 1] = h2pack(q1, q2);
            }
        }

        // ========= GEMM1: rows 16wp..+16, BOTH parities, all 32 c2 =========
        float acc1[2][4][4];   // [parity][nf][reg]
        #pragma unroll
        for (int p = 0; p < 2; p++)
            #pragma unroll
            for (int nf = 0; nf < 4; nf++)
                #pragma unroll
                for (int i = 0; i < 4; i++) acc1[p][nf][i] = 0.f;

        #pragma unroll
        for (int kt = 0; kt < 4; kt++) {
            uint32_t bA[4], bB[4];
            LDSM4(bA, b1b + kt * 32);                // c2 rows 0-15
            LDSM4(bB, b1b + 16 * S + kt * 32);       // c2 rows 16-31
            MMA(acc1[0][0], af0[kt], bA[0], bA[2]);
            MMA(acc1[0][1], af0[kt], bA[1], bA[3]);
            MMA(acc1[0][2], af0[kt], bB[0], bB[2]);
            MMA(acc1[0][3], af0[kt], bB[1], bB[3]);
            MMA(acc1[1][0], af1[kt], bA[0], bA[2]);
            MMA(acc1[1][1], af1[kt], bA[1], bA[3]);
            MMA(acc1[1][2], af1[kt], bB[0], bB[2]);
            MMA(acc1[1][3], af1[kt], bB[1], bB[3]);
        }

        // ---- in-register convert: D1 frags -> GEMM2 A frags (bias+relu+pack) ----
        uint32_t a2f[4][4];
        #pragma unroll
        for (int p = 0; p < 2; p++) {
            #pragma unroll
            for (int nf = 0; nf < 4; nf++) {
                int nfg = 4 * p + nf;               // GEMM1-output n-frag = GEMM2 k-frag
                float ba = cst[160 + 8 * nfg + 2 * tg];
                float bc = cst[160 + 8 * nfg + 2 * tg + 1];
                float f00 = fmaxf(acc1[p][nf][0] + ba, 0.f);
                float f01 = fmaxf(acc1[p][nf][1] + bc, 0.f);
                float f10 = fmaxf(acc1[p][nf][2] + ba, 0.f);
                float f11 = fmaxf(acc1[p][nf][3] + bc, 0.f);
                int kt = nfg >> 1, hh = nfg & 1;
                a2f[kt][2 * hh]     = h2pack(f00, f01);
                a2f[kt][2 * hh + 1] = h2pack(f10, f11);
            }
        }

        // ========= GEMM2: rows 16wp..+16, all 64 out cols (A in regs, B single) =========
        float acc2[8][4];
        #pragma unroll
        for (int nf = 0; nf < 8; nf++) {
            float p0 = cst[224 + 8 * nf + 2 * tg];
            float p1 = cst[224 + 8 * nf + 2 * tg + 1];
            acc2[nf][0] = p0; acc2[nf][1] = p1; acc2[nf][2] = p0; acc2[nf][3] = p1;
        }

        #pragma unroll
        for (int kt = 0; kt < 4; kt++) {
            #pragma unroll
            for (int grp = 0; grp < 4; grp++) {
                uint32_t bh[4];
                LDSM4(bh, b2b + grp * (16 * S) + kt * 32);
                MMA(acc2[2 * grp],     a2f[kt], bh[0], bh[2]);
                MMA(acc2[2 * grp + 1], a2f[kt], bh[1], bh[3]);
            }
        }

        // ---- epilogue: -> out (bias already in acc init) ----
        {
            size_t r0 = (size_t)tile * 64 + 16 * wp + g;
            #pragma unroll
            for (int nf = 0; nf < 8; nf++) {
                int ncol = 8 * nf + 2 * tg;
                *(float2*)(out + r0 * 64 + ncol)       = make_float2(acc2[nf][0], acc2[nf][1]);
                *(float2*)(out + (r0 + 8) * 64 + ncol) = make_float2(acc2[nf][2], acc2[nf][3]);
            }
        }
        // no barriers anywhere in the loop: warps are fully independent
    }
}

extern "C" void kernel_launch(void* const* d_in, const int* in_sizes, int n_in,
                              void* d_out, int out_size)
{
    const float* x  = (const float*)d_in[0];
    const float* W1 = (const float*)d_in[1];
    const float* b1 = (const float*)d_in[2];
    const float* W2 = (const float*)d_in[3];
    const float* b2 = (const float*)d_in[4];
    const float* Wp = (const float*)d_in[5];
    const float* bp = (const float*)d_in[6];
    float* out = (float*)d_out;

    cudaFuncSetAttribute(cnn_encoder_mma13,
                         cudaFuncAttributeMaxDynamicSharedMemorySize, SMEM_BYTES);

    cnn_encoder_mma13<<<GRID, THREADS, SMEM_BYTES>>>(x, W1, b1, W2, b2, Wp, bp, out);
}